// round 3
// baseline (speedup 1.0000x reference)
#include <cuda_runtime.h>
#include <cuda_fp16.h>

#define RES     256
#define CHOUT   16
#define NCH     128          // CH*RR phasor channels per plane
#define CPB     4            // FFT channels per block (low smem -> full sampler occupancy)
#define NPTS    262144
#define HPTS    131072
#define PI_F    3.14159265358979323846f

#define FXBLK   (NCH / CPB * 128)   // 4096 fft-x blocks
#define FYBLK   (NCH / CPB * 256)   // 8192 fft-y blocks
#define SHBLK   (HPTS / 8)          // 16384 sampler-half blocks

// Scratch (device globals: allocation-free rule)
__device__ float2 g_mid[128 * 256 * NCH];                 // [ky<128][x][ch] fp32, 33.5 MB
__device__ __half g_feat[2][RES * RES * 2 * NCH];         // ping-pong fp16 feat, 2x33.5 MB

__device__ __forceinline__ float2 cadd(float2 a, float2 b) { return make_float2(a.x + b.x, a.y + b.y); }
__device__ __forceinline__ float2 csub(float2 a, float2 b) { return make_float2(a.x - b.x, a.y - b.y); }
__device__ __forceinline__ float2 cmul(float2 a, float2 b) {
    return make_float2(fmaf(a.x, b.x, -a.y * b.y), fmaf(a.x, b.y, a.y * b.x));
}
__device__ __forceinline__ float2 muli(float2 a) { return make_float2(-a.y, a.x); }

// Bank-conflict swizzle: pure relabeling of smem element index (bijection on [0,256)).
__device__ __forceinline__ int sz(int e) { return e ^ (((e >> 4) & 3) << 2); }

// Radix-4 Stockham stage (inverse, +i). One butterfly per thread (CPB=4).
template<int NS>
__device__ __forceinline__ void stage4(float2 (*src)[257], float2 (*dst)[257],
                                       const float2* tw) {
    __syncthreads();
    int tid = threadIdx.x;
    int cc = tid >> 6, j = tid & 63;
    int jm = j & (NS - 1);
    float2 v0 = src[cc][sz(j)];
    float2 v1 = src[cc][sz(j + 64)];
    float2 v2 = src[cc][sz(j + 128)];
    float2 v3 = src[cc][sz(j + 192)];
    const int MS = 64 / NS;                 // tw[m] = exp(+2*pi*i*m/256)
    float2 w1 = tw[jm * MS];
    float2 w2 = tw[2 * jm * MS];
    float2 w3 = tw[3 * jm * MS];
    v1 = cmul(v1, w1); v2 = cmul(v2, w2); v3 = cmul(v3, w3);
    float2 a = cadd(v0, v2), b = csub(v0, v2);
    float2 c = cadd(v1, v3), d = muli(csub(v1, v3));
    int o = ((j & ~(NS - 1)) << 2) | jm;
    dst[cc][sz(o)]          = cadd(a, c);
    dst[cc][sz(o + NS)]     = cadd(b, d);
    dst[cc][sz(o + 2 * NS)] = csub(a, c);
    dst[cc][sz(o + 3 * NS)] = csub(b, d);
}

__device__ __forceinline__ void ld8h(const __half* p, float* f) {
    uint4 u = *(const uint4*)p;                 // 8 halves = 16B, aligned
    const half2* h = (const half2*)&u;
    float2 a = __half22float2(h[0]);
    float2 b = __half22float2(h[1]);
    float2 c = __half22float2(h[2]);
    float2 d = __half22float2(h[3]);
    f[0] = a.x; f[1] = a.y; f[2] = b.x; f[3] = b.y;
    f[4] = c.x; f[5] = c.y; f[6] = d.x; f[7] = d.y;
}

// ---------------------------------------------------------------------------
// Heterogeneous-block kernel: blocks [0, fft_nblk) do FFT (mode 1 = x-pass,
// mode 2 = y-pass); remaining blocks sample samp_pts points of plane fr.
// ---------------------------------------------------------------------------
__global__ void __launch_bounds__(256)
kmix(const float* __restrict__ P, int fft_mode, int fft_nblk,
     int fw, int fr,
     const float* __restrict__ inputs, float* __restrict__ out,
     int ix, int iy, int is, int accum, int samp_base, int samp_pts) {
    int tid = threadIdx.x;

    if ((int)blockIdx.x < fft_nblk) {
        // ===================== FFT role =====================
        __shared__ float2 sA[CPB][257];
        __shared__ float2 sB[CPB][257];
        __shared__ float2 tw[256];
        int bid = blockIdx.x;
        int g = bid & (NCH / CPB - 1);          // 32 channel groups
        int slice = bid / (NCH / CPB);          // ky (mode1) or x (mode2)
        {
            float sn, cs;
            sincosf(PI_F * (float)tid / 128.f, &sn, &cs);
            tw[tid] = make_float2(cs, sn);      // inverse: +i
        }
        int cc = tid >> 6, j = tid & 63;
        float2 v0, v1;
        if (fft_mode == 1) {
            const float2* row = (const float2*)P + ((size_t)(g * CPB + cc) * 256 + slice) * 256;
            v0 = row[j];                        // kx < 128 nonzero region
            v1 = row[j + 64];
        } else {
            int ch = g * CPB + cc;
            v0 = g_mid[((size_t)j * 256 + slice) * NCH + ch];
            v1 = g_mid[((size_t)(j + 64) * 256 + slice) * NCH + ch];
        }
        // Stage 0 (ns=1), specialized: top half of input is zero (v2=v3=0).
        sA[cc][sz(4 * j)]     = cadd(v0, v1);
        sA[cc][sz(4 * j + 1)] = cadd(v0, muli(v1));
        sA[cc][sz(4 * j + 2)] = csub(v0, v1);
        sA[cc][sz(4 * j + 3)] = csub(v0, muli(v1));
        stage4<4>(sA, sB, tw);
        stage4<16>(sB, sA, tw);
        stage4<64>(sA, sB, tw);
        __syncthreads();
        if (fft_mode == 1) {
            for (int idx = tid; idx < CPB * 256; idx += 256) {
                int c2 = idx & (CPB - 1), x = idx >> 2;
                g_mid[((size_t)slice * 256 + x) * NCH + g * CPB + c2] = sB[c2][sz(x)];
            }
        } else {
            for (int idx = tid; idx < CPB * 256; idx += 256) {
                int c2 = idx & (CPB - 1), y = idx >> 2;
                int ch = g * CPB + c2;
                float2 v = sB[c2][sz(y)];       // unnormalized (1/65536 deferred)
                __half2* fo = (__half2*)&g_feat[fw][(((y << 8) + slice) << 8) + 2 * ch];
                *fo = __floats2half2_rn(v.x, v.y);
            }
        }
        return;
    }

    // ===================== Sampler role =====================
    int wl = ((int)blockIdx.x - fft_nblk) * 8 + (tid >> 5);
    if (wl >= samp_pts) return;
    int pt = samp_base + wl;
    int lane = tid & 31;

    float gx = __ldg(inputs + pt * 3 + ix);
    float gy = __ldg(inputs + pt * 3 + iy);
    float ic = __ldg(inputs + pt * 3 + is);

    float xx = (gx + 1.f) * 127.5f;
    float yy = (gy + 1.f) * 127.5f;
    float xf = floorf(xx), yf = floorf(yy);
    float wx = xx - xf, wy = yy - yf;
    int x0 = min(max((int)xf, 0), 255);
    int x1 = min(x0 + 1, 255);
    int y0 = min(max((int)yf, 0), 255);
    int y1 = min(y0 + 1, 255);
    float w00 = (1.f - wx) * (1.f - wy);
    float w01 = wx * (1.f - wy);
    float w10 = (1.f - wx) * wy;
    float w11 = wx * wy;

    const __half* fb = g_feat[fr];
    int co = lane << 3;                         // lane t owns feat channels [8t,8t+8)
    float F[8], t[8];
    ld8h(fb + ((((y0 << 8) + x0) << 8) + co), t);
#pragma unroll
    for (int i = 0; i < 8; i++) F[i] = w00 * t[i];
    ld8h(fb + ((((y0 << 8) + x1) << 8) + co), t);
#pragma unroll
    for (int i = 0; i < 8; i++) F[i] = fmaf(w01, t[i], F[i]);
    ld8h(fb + ((((y1 << 8) + x0) << 8) + co), t);
#pragma unroll
    for (int i = 0; i < 8; i++) F[i] = fmaf(w10, t[i], F[i]);
    ld8h(fb + ((((y1 << 8) + x1) << 8) + co), t);
#pragma unroll
    for (int i = 0; i < 8; i++) F[i] = fmaf(w11, t[i], F[i]);

    // Fourier integration. theta_r = pi*s*(2^r-1)/128 via squaring recurrence.
    float s = (ic + 1.f) * 127.5f;
    float2 e1;
    sincosf(s * (PI_F / 128.f), &e1.y, &e1.x);
    bool re = (lane < 16);                      // lanes 0-15 real (cos), 16-31 imag (-sin)
    float val = re ? F[0] : 0.f;                // r=0: coef=0
    float2 u = e1;
#pragma unroll
    for (int r = 1; r < 8; r++) {
        val = fmaf(F[r], re ? u.x : -u.y, val);
        if (r < 7) u = cmul(cmul(u, u), e1);    // theta_{r+1} = 2*theta_r + theta_1
    }
    val += __shfl_down_sync(0xffffffffu, val, 16);
    if (lane < 16) {
        float v = val * (1.f / 65536.f);        // deferred ifft2 normalization
        float* o = out + pt * CHOUT + lane;
        if (accum) *o += v; else *o = v;
    }
}

// ---------------------------------------------------------------------------
extern "C" void kernel_launch(void* const* d_in, const int* in_sizes, int n_in,
                              void* d_out, int out_size) {
    const float* P0 = (const float*)d_in[0];
    const float* P1 = (const float*)d_in[1];
    const float* P2 = (const float*)d_in[2];
    const float* inp = (const float*)d_in[3];
    float* out = (float*)d_out;
    // Plane coordinate permutations: (gx, gy, s) indices into inputs[:,3]
    // Pu: {1,2,0}  Pv: {0,2,1}  Pw: {0,1,2}

    // L1: fftx(plane0)
    kmix<<<FXBLK, 256>>>(P0, 1, FXBLK, 0, 0, inp, out, 0, 0, 0, 0, 0, 0);
    // L2: ffty(plane0) -> feat0
    kmix<<<FYBLK, 256>>>(nullptr, 2, FYBLK, 0, 0, inp, out, 0, 0, 0, 0, 0, 0);
    // L3: fftx(plane1) + sample(plane0, half A)
    kmix<<<FXBLK + SHBLK, 256>>>(P1, 1, FXBLK, 0, 0, inp, out, 1, 2, 0, 0, 0, HPTS);
    // L4: ffty(plane1) -> feat1  + sample(plane0, half B)
    kmix<<<FYBLK + SHBLK, 256>>>(nullptr, 2, FYBLK, 1, 0, inp, out, 1, 2, 0, 0, HPTS, HPTS);
    // L5: fftx(plane2) + sample(plane1, half A)
    kmix<<<FXBLK + SHBLK, 256>>>(P2, 1, FXBLK, 0, 1, inp, out, 0, 2, 1, 1, 0, HPTS);
    // L6: ffty(plane2) -> feat0  + sample(plane1, half B)
    kmix<<<FYBLK + SHBLK, 256>>>(nullptr, 2, FYBLK, 0, 1, inp, out, 0, 2, 1, 1, HPTS, HPTS);
    // L7: sample(plane2, full)
    kmix<<<2 * SHBLK, 256>>>(nullptr, 0, 0, 0, 0, inp, out, 0, 1, 2, 1, 0, NPTS);
}

// round 4
// speedup vs baseline: 1.1975x; 1.1975x over previous
#include <cuda_runtime.h>
#include <cuda_fp16.h>

#define RES     256
#define CHOUT   16
#define NCH     128          // CH*RR phasor channels per plane
#define CPB     8            // FFT channels per block
#define NPTS    262144
#define NBIN    65536
#define PI_F    3.14159265358979323846f

// Scratch (device globals: allocation-free rule)
__device__ float2   g_mid[128 * 256 * NCH];        // [ky<128][x][ch] fp32, 33.5 MB
__device__ __half   g_feat[RES * RES * 2 * NCH];   // [y][x][256ch] fp16 unnormalized
__device__ unsigned g_hist[3][NBIN];
__device__ unsigned g_ofs [3][NBIN];
__device__ unsigned g_bsum[3][256];
__device__ float4   g_crd [3][NPTS];               // sorted (gx, gy, s, -) per plane
__device__ int      g_pid [3][NPTS];               // sorted original point id

__device__ __forceinline__ float2 cadd(float2 a, float2 b) { return make_float2(a.x + b.x, a.y + b.y); }
__device__ __forceinline__ float2 csub(float2 a, float2 b) { return make_float2(a.x - b.x, a.y - b.y); }
__device__ __forceinline__ float2 cmul(float2 a, float2 b) {
    return make_float2(fmaf(a.x, b.x, -a.y * b.y), fmaf(a.x, b.y, a.y * b.x));
}
__device__ __forceinline__ float2 muli(float2 a) { return make_float2(-a.y, a.x); }
__device__ __forceinline__ int sz(int e) { return e ^ (((e >> 4) & 3) << 2); }

// ===========================================================================
// FFT (identical structure to the proven R2 kernels)
// ===========================================================================
template<int NS>
__device__ __forceinline__ void stage4(float2 (*src)[257], float2 (*dst)[257],
                                       const float2* tw) {
    __syncthreads();
    int tid = threadIdx.x;
#pragma unroll
    for (int k = 0; k < 2; k++) {
        int idx = tid + (k << 8);
        int cc = idx >> 6, j = idx & 63;
        int jm = j & (NS - 1);
        float2 v0 = src[cc][sz(j)];
        float2 v1 = src[cc][sz(j + 64)];
        float2 v2 = src[cc][sz(j + 128)];
        float2 v3 = src[cc][sz(j + 192)];
        const int MS = 64 / NS;
        float2 w1 = tw[jm * MS];
        float2 w2 = tw[2 * jm * MS];
        float2 w3 = tw[3 * jm * MS];
        v1 = cmul(v1, w1); v2 = cmul(v2, w2); v3 = cmul(v3, w3);
        float2 a = cadd(v0, v2), b = csub(v0, v2);
        float2 c = cadd(v1, v3), d = muli(csub(v1, v3));
        int o = ((j & ~(NS - 1)) << 2) | jm;
        dst[cc][sz(o)]          = cadd(a, c);
        dst[cc][sz(o + NS)]     = cadd(b, d);
        dst[cc][sz(o + 2 * NS)] = csub(a, c);
        dst[cc][sz(o + 3 * NS)] = csub(b, d);
    }
}

__global__ void kfftx(const float* __restrict__ P) {
    __shared__ float2 sA[CPB][257];
    __shared__ float2 sB[CPB][257];
    __shared__ float2 tw[256];
    int tid = threadIdx.x, g = blockIdx.x, ky = blockIdx.y;
    {
        float sn, cs;
        sincosf(PI_F * (float)tid / 128.f, &sn, &cs);
        tw[tid] = make_float2(cs, sn);          // inverse: +i
    }
    const float2* Pf = (const float2*)P;
#pragma unroll
    for (int k = 0; k < 2; k++) {
        int idx = tid + (k << 8);
        int cc = idx >> 6, j = idx & 63;
        int ch = g * CPB + cc;
        const float2* row = Pf + ((size_t)ch * 256 + ky) * 256;
        float2 v0 = row[j], v1 = row[j + 64];
        sA[cc][sz(4 * j)]     = cadd(v0, v1);
        sA[cc][sz(4 * j + 1)] = cadd(v0, muli(v1));
        sA[cc][sz(4 * j + 2)] = csub(v0, v1);
        sA[cc][sz(4 * j + 3)] = csub(v0, muli(v1));
    }
    stage4<4>(sA, sB, tw);
    stage4<16>(sB, sA, tw);
    stage4<64>(sA, sB, tw);
    __syncthreads();
    for (int idx = tid; idx < CPB * 256; idx += 256) {
        int cc = idx & 7, x = idx >> 3;
        g_mid[((size_t)ky * 256 + x) * NCH + g * CPB + cc] = sB[cc][sz(x)];
    }
}

__global__ void kffty() {
    __shared__ float2 sA[CPB][257];
    __shared__ float2 sB[CPB][257];
    __shared__ float2 tw[256];
    int tid = threadIdx.x, g = blockIdx.x, x = blockIdx.y;
    {
        float sn, cs;
        sincosf(PI_F * (float)tid / 128.f, &sn, &cs);
        tw[tid] = make_float2(cs, sn);
    }
#pragma unroll
    for (int k = 0; k < 2; k++) {
        int idx = tid + (k << 8);
        int cc = idx & 7, j = idx >> 3;
        int ch = g * CPB + cc;
        float2 v0 = g_mid[((size_t)j * 256 + x) * NCH + ch];
        float2 v1 = g_mid[((size_t)(j + 64) * 256 + x) * NCH + ch];
        sA[cc][sz(4 * j)]     = cadd(v0, v1);
        sA[cc][sz(4 * j + 1)] = cadd(v0, muli(v1));
        sA[cc][sz(4 * j + 2)] = csub(v0, v1);
        sA[cc][sz(4 * j + 3)] = csub(v0, muli(v1));
    }
    stage4<4>(sA, sB, tw);
    stage4<16>(sB, sA, tw);
    stage4<64>(sA, sB, tw);
    __syncthreads();
    for (int idx = tid; idx < CPB * 256; idx += 256) {
        int cc = idx & 7, y = idx >> 3;
        int ch = g * CPB + cc;
        float2 v = sB[cc][sz(y)];
        __half2* fo = (__half2*)&g_feat[(((y << 8) + x) << 8) + 2 * ch];
        *fo = __floats2half2_rn(v.x, v.y);
    }
}

// ===========================================================================
// Counting sort of points by (y0,x0) texel bin, independently per plane.
// Exact reordering -> no numeric effect; creates L1/L2 texel reuse.
// ===========================================================================
__device__ __forceinline__ int binkey(float gx, float gy) {
    float xx = (gx + 1.f) * 127.5f;
    float yy = (gy + 1.f) * 127.5f;
    int x0 = min(max(__float2int_rd(xx), 0), 255);
    int y0 = min(max(__float2int_rd(yy), 0), 255);
    return (y0 << 8) | x0;
}
__device__ __forceinline__ void plane_coords(int p, float i0, float i1, float i2,
                                             float& gx, float& gy, float& s) {
    if (p == 0)      { gx = i1; gy = i2; s = i0; }
    else if (p == 1) { gx = i0; gy = i2; s = i1; }
    else             { gx = i0; gy = i1; s = i2; }
}

__global__ void kzero() {
    int i = blockIdx.x * blockDim.x + threadIdx.x;
    if (i < 3 * NBIN) ((unsigned*)g_hist)[i] = 0;
}

__global__ void khist(const float* __restrict__ inputs) {
    int pt = blockIdx.x * blockDim.x + threadIdx.x;
    float i0 = inputs[pt * 3 + 0];
    float i1 = inputs[pt * 3 + 1];
    float i2 = inputs[pt * 3 + 2];
#pragma unroll
    for (int p = 0; p < 3; p++) {
        float gx, gy, s;
        plane_coords(p, i0, i1, i2, gx, gy, s);
        atomicAdd(&g_hist[p][binkey(gx, gy)], 1u);
    }
}

// block-wide exclusive scan over 256 threads; returns exclusive prefix of v
__device__ unsigned blk_exscan(unsigned v) {
    __shared__ unsigned wsum[8];
    int lane = threadIdx.x & 31, w = threadIdx.x >> 5;
    unsigned inc = v;
#pragma unroll
    for (int d = 1; d < 32; d <<= 1) {
        unsigned n = __shfl_up_sync(0xffffffffu, inc, d);
        if (lane >= d) inc += n;
    }
    if (lane == 31) wsum[w] = inc;
    __syncthreads();
    if (w == 0 && lane < 8) {
        unsigned s = wsum[lane];
#pragma unroll
        for (int d = 1; d < 8; d <<= 1) {
            unsigned n = __shfl_up_sync(0xffu, s, d);
            if (lane >= d) s += n;
        }
        wsum[lane] = s;
    }
    __syncthreads();
    unsigned off = (w == 0) ? 0u : wsum[w - 1];
    return inc - v + off;
}

__global__ void kscanA() {   // grid (256, 3): per-chunk sums
    int p = blockIdx.y, b = blockIdx.x, t = threadIdx.x;
    unsigned v = g_hist[p][b * 256 + t];
    __shared__ unsigned red[256];
    red[t] = v; __syncthreads();
    for (int s = 128; s > 0; s >>= 1) {
        if (t < s) red[t] += red[t + s];
        __syncthreads();
    }
    if (t == 0) g_bsum[p][b] = red[0];
}
__global__ void kscanB() {   // grid (3): exclusive scan of 256 chunk sums
    int p = blockIdx.x, t = threadIdx.x;
    unsigned v = g_bsum[p][t];
    unsigned ex = blk_exscan(v);
    g_bsum[p][t] = ex;
}
__global__ void kscanC() {   // grid (256, 3): global exclusive bin offsets
    int p = blockIdx.y, b = blockIdx.x, t = threadIdx.x;
    unsigned v = g_hist[p][b * 256 + t];
    unsigned ex = blk_exscan(v);
    g_ofs[p][b * 256 + t] = ex + g_bsum[p][b];
}

__global__ void kscatter(const float* __restrict__ inputs) {
    int pt = blockIdx.x * blockDim.x + threadIdx.x;
    float i0 = inputs[pt * 3 + 0];
    float i1 = inputs[pt * 3 + 1];
    float i2 = inputs[pt * 3 + 2];
#pragma unroll
    for (int p = 0; p < 3; p++) {
        float gx, gy, s;
        plane_coords(p, i0, i1, i2, gx, gy, s);
        unsigned pos = atomicAdd(&g_ofs[p][binkey(gx, gy)], 1u);
        g_crd[p][pos] = make_float4(gx, gy, s, 0.f);
        g_pid[p][pos] = pt;
    }
}

// ===========================================================================
// Sampler: one warp per (sorted) point. Lane t owns channels [8t,8t+8);
// lanes 0-15 real block (cos), 16-31 imag block (-sin).
// ===========================================================================
__device__ __forceinline__ void ld8h(const __half* p, float* f) {
    uint4 u = *(const uint4*)p;
    const half2* h = (const half2*)&u;
    float2 a = __half22float2(h[0]);
    float2 b = __half22float2(h[1]);
    float2 c = __half22float2(h[2]);
    float2 d = __half22float2(h[3]);
    f[0] = a.x; f[1] = a.y; f[2] = b.x; f[3] = b.y;
    f[4] = c.x; f[5] = c.y; f[6] = d.x; f[7] = d.y;
}

__global__ void __launch_bounds__(256)
ksample(int p, float* __restrict__ out, int accum) {
    int wl = (blockIdx.x * blockDim.x + threadIdx.x) >> 5;
    int lane = threadIdx.x & 31;
    if (wl >= NPTS) return;

    float4 c4 = __ldg(&g_crd[p][wl]);           // uniform per warp (broadcast)
    int pid = __ldg(&g_pid[p][wl]);
    float gx = c4.x, gy = c4.y, ic = c4.z;

    float xx = (gx + 1.f) * 127.5f;
    float yy = (gy + 1.f) * 127.5f;
    float xf = floorf(xx), yf = floorf(yy);
    float wx = xx - xf, wy = yy - yf;
    int x0 = min(max((int)xf, 0), 255);
    int x1 = min(x0 + 1, 255);
    int y0 = min(max((int)yf, 0), 255);
    int y1 = min(y0 + 1, 255);
    float w00 = (1.f - wx) * (1.f - wy);
    float w01 = wx * (1.f - wy);
    float w10 = (1.f - wx) * wy;
    float w11 = wx * wy;

    int co = lane << 3;
    float F[8], t[8];
    ld8h(g_feat + ((((y0 << 8) + x0) << 8) + co), t);
#pragma unroll
    for (int i = 0; i < 8; i++) F[i] = w00 * t[i];
    ld8h(g_feat + ((((y0 << 8) + x1) << 8) + co), t);
#pragma unroll
    for (int i = 0; i < 8; i++) F[i] = fmaf(w01, t[i], F[i]);
    ld8h(g_feat + ((((y1 << 8) + x0) << 8) + co), t);
#pragma unroll
    for (int i = 0; i < 8; i++) F[i] = fmaf(w10, t[i], F[i]);
    ld8h(g_feat + ((((y1 << 8) + x1) << 8) + co), t);
#pragma unroll
    for (int i = 0; i < 8; i++) F[i] = fmaf(w11, t[i], F[i]);

    float s = (ic + 1.f) * 127.5f;
    float2 e1;
    sincosf(s * (PI_F / 128.f), &e1.y, &e1.x);  // theta_1 = pi*s/128
    bool re = (lane < 16);
    float val = re ? F[0] : 0.f;                // r=0: coef=0
    float2 u = e1;
#pragma unroll
    for (int r = 1; r < 8; r++) {
        val = fmaf(F[r], re ? u.x : -u.y, val);
        if (r < 7) u = cmul(cmul(u, u), e1);    // theta_{r+1}=2*theta_r+theta_1
    }
    val += __shfl_down_sync(0xffffffffu, val, 16);
    if (lane < 16) {
        float v = val * (1.f / 65536.f);        // deferred ifft2 normalization
        float* o = out + pid * CHOUT + lane;
        if (accum) *o += v; else *o = v;
    }
}

// ---------------------------------------------------------------------------
extern "C" void kernel_launch(void* const* d_in, const int* in_sizes, int n_in,
                              void* d_out, int out_size) {
    const float* inp = (const float*)d_in[3];
    float* out = (float*)d_out;

    // Point sort (plane-independent of P data): bins by texel for locality.
    kzero<<<(3 * NBIN + 1023) / 1024, 1024>>>();
    khist<<<NPTS / 256, 256>>>(inp);
    kscanA<<<dim3(256, 3), 256>>>();
    kscanB<<<3, 256>>>();
    kscanC<<<dim3(256, 3), 256>>>();
    kscatter<<<NPTS / 256, 256>>>(inp);

    for (int p = 0; p < 3; p++) {
        const float* P = (const float*)d_in[p];
        kfftx<<<dim3(NCH / CPB, 128), 256>>>(P);
        kffty<<<dim3(NCH / CPB, RES), 256>>>();
        ksample<<<NPTS / 8, 256>>>(p, out, p > 0);
    }
}